// round 14
// baseline (speedup 1.0000x reference)
#include <cuda_runtime.h>
#include <cuda_bf16.h>
#include <cstdint>

// ---------------- problem constants ----------------
#define B_ROWS   4096
#define HALF_DIM 1024
#define MID_DIM  4096
#define NH       4

// ---------------- scratch (device globals; no cudaMalloc allowed) ----------
__device__ __nv_bfloat16 g_x2[(size_t)B_ROWS * HALF_DIM];            //  8 MB
__device__ __nv_bfloat16 g_h0[(size_t)B_ROWS * MID_DIM];             // 32 MB
__device__ __nv_bfloat16 g_h1[(size_t)B_ROWS * MID_DIM];             // 32 MB
__device__ __nv_bfloat16 g_wt[(size_t)HALF_DIM * MID_DIM +
                              (size_t)NH * MID_DIM * MID_DIM +
                              (size_t)MID_DIM * HALF_DIM];           // 151 MB ([K,N] layout)

// ---------------- helpers ----------------
__device__ __forceinline__ uint32_t smem_u32(const void* p) {
    uint32_t a;
    asm("{ .reg .u64 t; cvta.to.shared.u64 t, %1; cvt.u32.u64 %0, t; }"
        : "=r"(a) : "l"(p));
    return a;
}

#define CP_ASYNC16(dst_u32, src_ptr) \
    asm volatile("cp.async.cg.shared.global [%0], [%1], 16;" \
        :: "r"(dst_u32), "l"(src_ptr) : "memory")
#define CP_COMMIT() asm volatile("cp.async.commit_group;" ::: "memory")
#define CP_WAIT2()  asm volatile("cp.async.wait_group 2;"  ::: "memory")
#define CP_WAIT0()  asm volatile("cp.async.wait_group 0;"  ::: "memory")

#define LDSM_X4(r0, r1, r2, r3, addr) \
    asm volatile("ldmatrix.sync.aligned.m8n8.x4.shared.b16 {%0,%1,%2,%3}, [%4];" \
        : "=r"(r0), "=r"(r1), "=r"(r2), "=r"(r3) : "r"(addr))

#define LDSM_X4_T(r0, r1, r2, r3, addr) \
    asm volatile("ldmatrix.sync.aligned.m8n8.x4.trans.shared.b16 {%0,%1,%2,%3}, [%4];" \
        : "=r"(r0), "=r"(r1), "=r"(r2), "=r"(r3) : "r"(addr))

__device__ __forceinline__ void mma_bf16(float* d, const uint32_t* a, const uint32_t* b) {
    asm volatile(
        "mma.sync.aligned.m16n8k16.row.col.f32.bf16.bf16.f32 "
        "{%0,%1,%2,%3}, {%4,%5,%6,%7}, {%8,%9}, {%0,%1,%2,%3};"
        : "+f"(d[0]), "+f"(d[1]), "+f"(d[2]), "+f"(d[3])
        : "r"(a[0]), "r"(a[1]), "r"(a[2]), "r"(a[3]), "r"(b[0]), "r"(b[1]));
}

// ---------------- prologue kernels ----------------
__global__ void prep_x2(const float* __restrict__ x, const float* __restrict__ ldj,
                        __nv_bfloat16* __restrict__ x2, float* __restrict__ yout,
                        int write_ldj) {
    size_t i = (size_t)blockIdx.x * blockDim.x + threadIdx.x;
    float2 p = ((const float2*)x)[i];
    x2[i] = __float2bfloat16(p.y);
    if (i == 0 && write_ldj) yout[(size_t)B_ROWS * 2 * HALF_DIM] = ldj[0];
}

// fp32 -> bf16 streaming convert, 4x float4 per thread (block covers 4096 floats)
__global__ void convert_bf16(const float* __restrict__ in, __nv_bfloat16* __restrict__ out) {
    size_t base = (size_t)blockIdx.x * 1024 + threadIdx.x;     // float4 units
    #pragma unroll
    for (int k = 0; k < 4; k++) {
        float4 v = ((const float4*)in)[base + (size_t)k * 256];
        __nv_bfloat162* o = (__nv_bfloat162*)out + 2 * (base + (size_t)k * 256);
        o[0] = __floats2bfloat162_rn(v.x, v.y);
        o[1] = __floats2bfloat162_rn(v.z, v.w);
    }
}

// ---------------- bf16 mma.sync GEMM (round-9 structure, unrolled x4 mainloop) ----
// C[M,N] = epi( A[M,K] @ W[K,N] + bias ); A K-major bf16, W [K,N] row-major bf16.
// Tile 64x128, KC=64, 4-stage cp.async pipeline, 128 threads (2x2 warps),
// warp tile 32x64; A via ldmatrix, W via ldmatrix.trans.
#define TM 64
#define TN 128
#define KC 64
#define STAGES 4
#define AROWB 144
#define BROWB 272
#define A_TILE (64 * AROWB)
#define B_TILE (KC * BROWB)
#define STG_BYTES (A_TILE + B_TILE)
#define GEMM_SMEM (STAGES * STG_BYTES)             // 106496

__global__ void __launch_bounds__(128, 2)
gemm_bf16(const __nv_bfloat16* __restrict__ A, const __nv_bfloat16* __restrict__ W,
          const float* __restrict__ bias, __nv_bfloat16* __restrict__ C,
          const float* __restrict__ xin, float* __restrict__ yout,
          int K, int N, int n_chunks, int mode) {
    extern __shared__ char smem[];
    const uint32_t sbase = smem_u32(smem);
    const int tid  = threadIdx.x;
    const int wid  = tid >> 5;
    const int lane = tid & 31;
    const int wm   = wid >> 1;              // 0..1 -> M halves (32 rows)
    const int wn   = wid & 1;               // 0..1 -> N halves (64 cols)
    const int gid  = lane >> 2;
    const int tg   = lane & 3;
    const int m0   = blockIdx.y * TM;
    const int n0   = blockIdx.x * TN;

    const __nv_bfloat16* ag0 = A + (size_t)m0 * K;
    const __nv_bfloat16* bg0 = W + n0;

    const uint32_t a_off = (uint32_t)((wm * 32 + (lane & 15)) * AROWB + (lane >> 4) * 16);
    const int krow = (lane & 7) | (((lane >> 3) & 1) << 3);
    const uint32_t b_off = (uint32_t)(krow * BROWB + wn * 128 + (lane >> 4) * 16);

    auto load_stage = [&](int s, int c) {
        const __nv_bfloat16* ag = ag0 + (size_t)c * KC;
        const __nv_bfloat16* bg = bg0 + (size_t)c * KC * N;
        const uint32_t sa = sbase + (uint32_t)s * STG_BYTES;
        const uint32_t sb = sa + A_TILE;
        #pragma unroll
        for (int i = 0; i < 4; i++) {                 // A: 64 rows x 8 x 16B
            int id  = tid + 128 * i;
            int row = id >> 3, col = id & 7;
            CP_ASYNC16(sa + (uint32_t)(row * AROWB + col * 16),
                       ag + (size_t)row * K + col * 8);
        }
        #pragma unroll
        for (int i = 0; i < 8; i++) {                 // B: 64 rows x 16 x 16B
            int id  = tid + 128 * i;
            int row = id >> 4, col = id & 15;
            CP_ASYNC16(sb + (uint32_t)(row * BROWB + col * 16),
                       bg + (size_t)row * N + col * 8);
        }
        CP_COMMIT();
    };

    float acc[2][8][4];
    #pragma unroll
    for (int i = 0; i < 2; i++)
        #pragma unroll
        for (int j = 0; j < 8; j++)
            #pragma unroll
            for (int v = 0; v < 4; v++) acc[i][j][v] = 0.f;

    load_stage(0, 0);
    load_stage(1, 1);
    load_stage(2, 2);

    // n_chunks is 16 or 64 -> divisible by 4; unroll x4 makes stage indices
    // (c & 3) compile-time constants per body, removing wrap/base-math overhead.
    #pragma unroll 4
    for (int c = 0; c < n_chunks; c++) {
        const int s = c & (STAGES - 1);
        CP_WAIT2();
        __syncthreads();
        if (c + 3 < n_chunks)
            load_stage((c + 3) & (STAGES - 1), c + 3);
        const uint32_t sa = sbase + (uint32_t)s * STG_BYTES;
        const uint32_t sb = sa + A_TILE;

        #pragma unroll
        for (int ks = 0; ks < KC / 16; ks++) {
            uint32_t af[2][4], bf[4][4];
            #pragma unroll
            for (int mt = 0; mt < 2; mt++)
                LDSM_X4(af[mt][0], af[mt][1], af[mt][2], af[mt][3],
                        sa + a_off + (uint32_t)(mt * 16 * AROWB + ks * 32));
            #pragma unroll
            for (int np = 0; np < 4; np++)
                LDSM_X4_T(bf[np][0], bf[np][1], bf[np][2], bf[np][3],
                          sb + b_off + (uint32_t)(ks * 16 * BROWB + np * 32));
            #pragma unroll
            for (int mt = 0; mt < 2; mt++)
                #pragma unroll
                for (int nt = 0; nt < 8; nt++)
                    mma_bf16(acc[mt][nt], af[mt], &bf[nt >> 1][(nt & 1) * 2]);
        }
    }
    CP_WAIT0();

    // ---- epilogue ----
    if (mode == 0) {
        #pragma unroll
        for (int mt = 0; mt < 2; mt++) {
            int r = m0 + wm * 32 + mt * 16 + gid;
            #pragma unroll
            for (int nt = 0; nt < 8; nt++) {
                int cb = n0 + wn * 64 + nt * 8 + 2 * tg;
                float b0 = bias[cb], b1 = bias[cb + 1];
                __nv_bfloat162 v0 = __floats2bfloat162_rn(
                    fmaxf(acc[mt][nt][0] + b0, 0.f), fmaxf(acc[mt][nt][1] + b1, 0.f));
                __nv_bfloat162 v1 = __floats2bfloat162_rn(
                    fmaxf(acc[mt][nt][2] + b0, 0.f), fmaxf(acc[mt][nt][3] + b1, 0.f));
                *(__nv_bfloat162*)(C + (size_t)r * MID_DIM + cb)       = v0;
                *(__nv_bfloat162*)(C + (size_t)(r + 8) * MID_DIM + cb) = v1;
            }
        }
    } else {
        #pragma unroll
        for (int mt = 0; mt < 2; mt++) {
            int r = m0 + wm * 32 + mt * 16 + gid;
            #pragma unroll
            for (int nt = 0; nt < 8; nt++) {
                int cb = n0 + wn * 64 + nt * 8 + 2 * tg;
                float b0 = bias[cb], b1 = bias[cb + 1];
                {
                    const float4 xv = *(const float4*)(xin + (size_t)r * 2 * HALF_DIM + 2 * cb);
                    float4 yv;
                    yv.x = xv.x + acc[mt][nt][0] + b0;
                    yv.y = xv.y;
                    yv.z = xv.z + acc[mt][nt][1] + b1;
                    yv.w = xv.w;
                    *(float4*)(yout + (size_t)r * 2 * HALF_DIM + 2 * cb) = yv;
                }
                {
                    const float4 xv = *(const float4*)(xin + (size_t)(r + 8) * 2 * HALF_DIM + 2 * cb);
                    float4 yv;
                    yv.x = xv.x + acc[mt][nt][2] + b0;
                    yv.y = xv.y;
                    yv.z = xv.z + acc[mt][nt][3] + b1;
                    yv.w = xv.w;
                    *(float4*)(yout + (size_t)(r + 8) * 2 * HALF_DIM + 2 * cb) = yv;
                }
            }
        }
    }
}

// ---------------- host ----------------
extern "C" void kernel_launch(void* const* d_in, const int* in_sizes, int n_in,
                              void* d_out, int out_size) {
    const float* x     = (const float*)d_in[0];
    const float* ldj   = (const float*)d_in[1];
    const float* W_in  = (const float*)d_in[2];
    const float* b_in  = (const float*)d_in[3];
    const float* W_h   = (const float*)d_in[4];
    const float* b_h   = (const float*)d_in[5];
    const float* W_out = (const float*)d_in[6];
    const float* b_out = (const float*)d_in[7];
    float* y = (float*)d_out;
    (void)in_sizes; (void)n_in;

    __nv_bfloat16 *px2, *ph0, *ph1, *pwt;
    cudaGetSymbolAddress((void**)&px2, g_x2);
    cudaGetSymbolAddress((void**)&ph0, g_h0);
    cudaGetSymbolAddress((void**)&ph1, g_h1);
    cudaGetSymbolAddress((void**)&pwt, g_wt);

    cudaFuncSetAttribute(gemm_bf16, cudaFuncAttributeMaxDynamicSharedMemorySize, GEMM_SMEM);

    static cudaStream_t s1 = nullptr;
    static cudaEvent_t ev_fork, ev_w[6];
    if (s1 == nullptr) {
        cudaStreamCreateWithFlags(&s1, cudaStreamNonBlocking);
        cudaEventCreateWithFlags(&ev_fork, cudaEventDisableTiming);
        for (int i = 0; i < 6; i++)
            cudaEventCreateWithFlags(&ev_w[i], cudaEventDisableTiming);
    }

    const size_t OFF_WIN  = 0;
    const size_t OFF_WH   = (size_t)HALF_DIM * MID_DIM;
    const size_t OFF_WOUT = OFF_WH + (size_t)NH * MID_DIM * MID_DIM;

    int write_ldj = (out_size > B_ROWS * 2 * HALF_DIM) ? 1 : 0;

    // main stream: x2 extraction
    prep_x2<<<(B_ROWS * HALF_DIM) / 256, 256>>>(x, ldj, px2, y, write_ldj);

    // fork side stream for weight converts
    cudaEventRecord(ev_fork, 0);
    cudaStreamWaitEvent(s1, ev_fork, 0);

    convert_bf16<<<(HALF_DIM * MID_DIM) / 4096, 256, 0, s1>>>(W_in, pwt + OFF_WIN);
    cudaEventRecord(ev_w[0], s1);
    for (int i = 0; i < NH; i++) {
        convert_bf16<<<(MID_DIM * MID_DIM) / 4096, 256, 0, s1>>>(
            W_h + (size_t)i * MID_DIM * MID_DIM, pwt + OFF_WH + (size_t)i * MID_DIM * MID_DIM);
        cudaEventRecord(ev_w[1 + i], s1);
    }
    convert_bf16<<<(MID_DIM * HALF_DIM) / 4096, 256, 0, s1>>>(W_out, pwt + OFF_WOUT);
    cudaEventRecord(ev_w[5], s1);

    // L1: h0 = relu(x2 @ W_in + b_in)   [M=4096, N=4096, K=1024]
    cudaStreamWaitEvent(0, ev_w[0], 0);
    gemm_bf16<<<dim3(MID_DIM / TN, B_ROWS / TM), 128, GEMM_SMEM>>>(
        px2, pwt + OFF_WIN, b_in, ph0, nullptr, nullptr,
        HALF_DIM, MID_DIM, HALF_DIM / KC, 0);

    // hidden layers [4096,4096,4096]
    for (int i = 0; i < NH; i++) {
        const __nv_bfloat16* Ain = (i % 2 == 0) ? ph0 : ph1;
        __nv_bfloat16* Cc        = (i % 2 == 0) ? ph1 : ph0;
        cudaStreamWaitEvent(0, ev_w[1 + i], 0);
        gemm_bf16<<<dim3(MID_DIM / TN, B_ROWS / TM), 128, GEMM_SMEM>>>(
            Ain, pwt + OFF_WH + (size_t)i * MID_DIM * MID_DIM,
            b_h + (size_t)i * MID_DIM, Cc, nullptr, nullptr,
            MID_DIM, MID_DIM, MID_DIM / KC, 0);
    }

    // L6: y = interleave(x1 + h @ W_out + b_out, x2)   [M=4096, N=1024, K=4096]
    cudaStreamWaitEvent(0, ev_w[5], 0);
    gemm_bf16<<<dim3(HALF_DIM / TN, B_ROWS / TM), 128, GEMM_SMEM>>>(
        ph0, pwt + OFF_WOUT, b_out, nullptr, x, y,
        MID_DIM, HALF_DIM, MID_DIM / KC, 1);
}

// round 15
// speedup vs baseline: 1.2105x; 1.2105x over previous
#include <cuda_runtime.h>
#include <cuda_bf16.h>
#include <cstdint>

// ---------------- problem constants ----------------
#define B_ROWS   4096
#define HALF_DIM 1024
#define MID_DIM  4096
#define NH       4

// ---------------- scratch (device globals; no cudaMalloc allowed) ----------
__device__ __nv_bfloat16 g_x2[(size_t)B_ROWS * HALF_DIM];            //  8 MB
__device__ __nv_bfloat16 g_h0[(size_t)B_ROWS * MID_DIM];             // 32 MB
__device__ __nv_bfloat16 g_h1[(size_t)B_ROWS * MID_DIM];             // 32 MB
__device__ __nv_bfloat16 g_wt[(size_t)HALF_DIM * MID_DIM +
                              (size_t)NH * MID_DIM * MID_DIM +
                              (size_t)MID_DIM * HALF_DIM];           // 151 MB ([K,N] layout)

// ---------------- helpers ----------------
__device__ __forceinline__ uint32_t smem_u32(const void* p) {
    uint32_t a;
    asm("{ .reg .u64 t; cvta.to.shared.u64 t, %1; cvt.u32.u64 %0, t; }"
        : "=r"(a) : "l"(p));
    return a;
}

#define CP_ASYNC16(dst_u32, src_ptr) \
    asm volatile("cp.async.cg.shared.global [%0], [%1], 16;" \
        :: "r"(dst_u32), "l"(src_ptr) : "memory")
#define CP_COMMIT() asm volatile("cp.async.commit_group;" ::: "memory")
#define CP_WAIT2()  asm volatile("cp.async.wait_group 2;"  ::: "memory")
#define CP_WAIT0()  asm volatile("cp.async.wait_group 0;"  ::: "memory")

#define LDSM_X4(r0, r1, r2, r3, addr) \
    asm volatile("ldmatrix.sync.aligned.m8n8.x4.shared.b16 {%0,%1,%2,%3}, [%4];" \
        : "=r"(r0), "=r"(r1), "=r"(r2), "=r"(r3) : "r"(addr))

#define LDSM_X4_T(r0, r1, r2, r3, addr) \
    asm volatile("ldmatrix.sync.aligned.m8n8.x4.trans.shared.b16 {%0,%1,%2,%3}, [%4];" \
        : "=r"(r0), "=r"(r1), "=r"(r2), "=r"(r3) : "r"(addr))

__device__ __forceinline__ void mma_bf16(float* d, const uint32_t* a, const uint32_t* b) {
    asm volatile(
        "mma.sync.aligned.m16n8k16.row.col.f32.bf16.bf16.f32 "
        "{%0,%1,%2,%3}, {%4,%5,%6,%7}, {%8,%9}, {%0,%1,%2,%3};"
        : "+f"(d[0]), "+f"(d[1]), "+f"(d[2]), "+f"(d[3])
        : "r"(a[0]), "r"(a[1]), "r"(a[2]), "r"(a[3]), "r"(b[0]), "r"(b[1]));
}

// ---------------- prologue kernels ----------------
__global__ void prep_x2(const float* __restrict__ x, const float* __restrict__ ldj,
                        __nv_bfloat16* __restrict__ x2, float* __restrict__ yout,
                        int write_ldj) {
    size_t i = (size_t)blockIdx.x * blockDim.x + threadIdx.x;
    float2 p = ((const float2*)x)[i];
    x2[i] = __float2bfloat16(p.y);
    if (i == 0 && write_ldj) yout[(size_t)B_ROWS * 2 * HALF_DIM] = ldj[0];
}

// fp32 -> bf16 streaming convert, 4x float4 per thread (block covers 4096 floats)
__global__ void convert_bf16(const float* __restrict__ in, __nv_bfloat16* __restrict__ out) {
    size_t base = (size_t)blockIdx.x * 1024 + threadIdx.x;     // float4 units
    #pragma unroll
    for (int k = 0; k < 4; k++) {
        float4 v = ((const float4*)in)[base + (size_t)k * 256];
        __nv_bfloat162* o = (__nv_bfloat162*)out + 2 * (base + (size_t)k * 256);
        o[0] = __floats2bfloat162_rn(v.x, v.y);
        o[1] = __floats2bfloat162_rn(v.z, v.w);
    }
}

// ---------------- bf16 mma.sync GEMM (verified best: 1636.4 us) ----------------
// C[M,N] = epi( A[M,K] @ W[K,N] + bias ); A K-major bf16, W [K,N] row-major bf16.
// Tile 64x128, KC=64, 4-stage cp.async pipeline, 128 threads (2x2 warps),
// warp tile 32x64; A via ldmatrix, W via ldmatrix.trans.
#define TM 64
#define TN 128
#define KC 64
#define STAGES 4
#define AROWB 144
#define BROWB 272
#define A_TILE (64 * AROWB)
#define B_TILE (KC * BROWB)
#define STG_BYTES (A_TILE + B_TILE)
#define GEMM_SMEM (STAGES * STG_BYTES)             // 106496

__global__ void __launch_bounds__(128, 2)
gemm_bf16(const __nv_bfloat16* __restrict__ A, const __nv_bfloat16* __restrict__ W,
          const float* __restrict__ bias, __nv_bfloat16* __restrict__ C,
          const float* __restrict__ xin, float* __restrict__ yout,
          int K, int N, int n_chunks, int mode) {
    extern __shared__ char smem[];
    const uint32_t sbase = smem_u32(smem);
    const int tid  = threadIdx.x;
    const int wid  = tid >> 5;
    const int lane = tid & 31;
    const int wm   = wid >> 1;              // 0..1 -> M halves (32 rows)
    const int wn   = wid & 1;               // 0..1 -> N halves (64 cols)
    const int gid  = lane >> 2;
    const int tg   = lane & 3;
    const int m0   = blockIdx.y * TM;
    const int n0   = blockIdx.x * TN;

    const __nv_bfloat16* ag0 = A + (size_t)m0 * K;
    const __nv_bfloat16* bg0 = W + n0;

    const uint32_t a_off = (uint32_t)((wm * 32 + (lane & 15)) * AROWB + (lane >> 4) * 16);
    const int krow = (lane & 7) | (((lane >> 3) & 1) << 3);
    const uint32_t b_off = (uint32_t)(krow * BROWB + wn * 128 + (lane >> 4) * 16);

    auto load_stage = [&](int s, int c) {
        const __nv_bfloat16* ag = ag0 + (size_t)c * KC;
        const __nv_bfloat16* bg = bg0 + (size_t)c * KC * N;
        const uint32_t sa = sbase + (uint32_t)s * STG_BYTES;
        const uint32_t sb = sa + A_TILE;
        #pragma unroll
        for (int i = 0; i < 4; i++) {                 // A: 64 rows x 8 x 16B
            int id  = tid + 128 * i;
            int row = id >> 3, col = id & 7;
            CP_ASYNC16(sa + (uint32_t)(row * AROWB + col * 16),
                       ag + (size_t)row * K + col * 8);
        }
        #pragma unroll
        for (int i = 0; i < 8; i++) {                 // B: 64 rows x 16 x 16B
            int id  = tid + 128 * i;
            int row = id >> 4, col = id & 15;
            CP_ASYNC16(sb + (uint32_t)(row * BROWB + col * 16),
                       bg + (size_t)row * N + col * 8);
        }
        CP_COMMIT();
    };

    float acc[2][8][4];
    #pragma unroll
    for (int i = 0; i < 2; i++)
        #pragma unroll
        for (int j = 0; j < 8; j++)
            #pragma unroll
            for (int v = 0; v < 4; v++) acc[i][j][v] = 0.f;

    load_stage(0, 0);
    load_stage(1, 1);
    load_stage(2, 2);

    int s = 0;
    for (int c = 0; c < n_chunks; c++) {
        CP_WAIT2();
        __syncthreads();
        if (c + 3 < n_chunks) {
            int s2 = s + 3; if (s2 >= STAGES) s2 -= STAGES;
            load_stage(s2, c + 3);
        }
        const uint32_t sa = sbase + (uint32_t)s * STG_BYTES;
        const uint32_t sb = sa + A_TILE;

        #pragma unroll
        for (int ks = 0; ks < KC / 16; ks++) {
            uint32_t af[2][4], bf[4][4];
            #pragma unroll
            for (int mt = 0; mt < 2; mt++)
                LDSM_X4(af[mt][0], af[mt][1], af[mt][2], af[mt][3],
                        sa + a_off + (uint32_t)(mt * 16 * AROWB + ks * 32));
            #pragma unroll
            for (int np = 0; np < 4; np++)
                LDSM_X4_T(bf[np][0], bf[np][1], bf[np][2], bf[np][3],
                          sb + b_off + (uint32_t)(ks * 16 * BROWB + np * 32));
            #pragma unroll
            for (int mt = 0; mt < 2; mt++)
                #pragma unroll
                for (int nt = 0; nt < 8; nt++)
                    mma_bf16(acc[mt][nt], af[mt], &bf[nt >> 1][(nt & 1) * 2]);
        }
        if (++s == STAGES) s = 0;
    }
    CP_WAIT0();

    // ---- epilogue ----
    if (mode == 0) {
        #pragma unroll
        for (int mt = 0; mt < 2; mt++) {
            int r = m0 + wm * 32 + mt * 16 + gid;
            #pragma unroll
            for (int nt = 0; nt < 8; nt++) {
                int cb = n0 + wn * 64 + nt * 8 + 2 * tg;
                float b0 = bias[cb], b1 = bias[cb + 1];
                __nv_bfloat162 v0 = __floats2bfloat162_rn(
                    fmaxf(acc[mt][nt][0] + b0, 0.f), fmaxf(acc[mt][nt][1] + b1, 0.f));
                __nv_bfloat162 v1 = __floats2bfloat162_rn(
                    fmaxf(acc[mt][nt][2] + b0, 0.f), fmaxf(acc[mt][nt][3] + b1, 0.f));
                *(__nv_bfloat162*)(C + (size_t)r * MID_DIM + cb)       = v0;
                *(__nv_bfloat162*)(C + (size_t)(r + 8) * MID_DIM + cb) = v1;
            }
        }
    } else {
        #pragma unroll
        for (int mt = 0; mt < 2; mt++) {
            int r = m0 + wm * 32 + mt * 16 + gid;
            #pragma unroll
            for (int nt = 0; nt < 8; nt++) {
                int cb = n0 + wn * 64 + nt * 8 + 2 * tg;
                float b0 = bias[cb], b1 = bias[cb + 1];
                {
                    const float4 xv = *(const float4*)(xin + (size_t)r * 2 * HALF_DIM + 2 * cb);
                    float4 yv;
                    yv.x = xv.x + acc[mt][nt][0] + b0;
                    yv.y = xv.y;
                    yv.z = xv.z + acc[mt][nt][1] + b1;
                    yv.w = xv.w;
                    *(float4*)(yout + (size_t)r * 2 * HALF_DIM + 2 * cb) = yv;
                }
                {
                    const float4 xv = *(const float4*)(xin + (size_t)(r + 8) * 2 * HALF_DIM + 2 * cb);
                    float4 yv;
                    yv.x = xv.x + acc[mt][nt][2] + b0;
                    yv.y = xv.y;
                    yv.z = xv.z + acc[mt][nt][3] + b1;
                    yv.w = xv.w;
                    *(float4*)(yout + (size_t)(r + 8) * 2 * HALF_DIM + 2 * cb) = yv;
                }
            }
        }
    }
}

// ---------------- host ----------------
extern "C" void kernel_launch(void* const* d_in, const int* in_sizes, int n_in,
                              void* d_out, int out_size) {
    const float* x     = (const float*)d_in[0];
    const float* ldj   = (const float*)d_in[1];
    const float* W_in  = (const float*)d_in[2];
    const float* b_in  = (const float*)d_in[3];
    const float* W_h   = (const float*)d_in[4];
    const float* b_h   = (const float*)d_in[5];
    const float* W_out = (const float*)d_in[6];
    const float* b_out = (const float*)d_in[7];
    float* y = (float*)d_out;
    (void)in_sizes; (void)n_in;

    __nv_bfloat16 *px2, *ph0, *ph1, *pwt;
    cudaGetSymbolAddress((void**)&px2, g_x2);
    cudaGetSymbolAddress((void**)&ph0, g_h0);
    cudaGetSymbolAddress((void**)&ph1, g_h1);
    cudaGetSymbolAddress((void**)&pwt, g_wt);

    cudaFuncSetAttribute(gemm_bf16, cudaFuncAttributeMaxDynamicSharedMemorySize, GEMM_SMEM);

    static cudaStream_t s1 = nullptr;
    static cudaEvent_t ev_fork, ev_w[6];
    if (s1 == nullptr) {
        cudaStreamCreateWithFlags(&s1, cudaStreamNonBlocking);
        cudaEventCreateWithFlags(&ev_fork, cudaEventDisableTiming);
        for (int i = 0; i < 6; i++)
            cudaEventCreateWithFlags(&ev_w[i], cudaEventDisableTiming);
    }

    const size_t OFF_WIN  = 0;
    const size_t OFF_WH   = (size_t)HALF_DIM * MID_DIM;
    const size_t OFF_WOUT = OFF_WH + (size_t)NH * MID_DIM * MID_DIM;

    int write_ldj = (out_size > B_ROWS * 2 * HALF_DIM) ? 1 : 0;

    // main stream: x2 extraction
    prep_x2<<<(B_ROWS * HALF_DIM) / 256, 256>>>(x, ldj, px2, y, write_ldj);

    // fork side stream for weight converts
    cudaEventRecord(ev_fork, 0);
    cudaStreamWaitEvent(s1, ev_fork, 0);

    convert_bf16<<<(HALF_DIM * MID_DIM) / 4096, 256, 0, s1>>>(W_in, pwt + OFF_WIN);
    cudaEventRecord(ev_w[0], s1);
    for (int i = 0; i < NH; i++) {
        convert_bf16<<<(MID_DIM * MID_DIM) / 4096, 256, 0, s1>>>(
            W_h + (size_t)i * MID_DIM * MID_DIM, pwt + OFF_WH + (size_t)i * MID_DIM * MID_DIM);
        cudaEventRecord(ev_w[1 + i], s1);
    }
    convert_bf16<<<(MID_DIM * HALF_DIM) / 4096, 256, 0, s1>>>(W_out, pwt + OFF_WOUT);
    cudaEventRecord(ev_w[5], s1);

    // L1: h0 = relu(x2 @ W_in + b_in)   [M=4096, N=4096, K=1024]
    cudaStreamWaitEvent(0, ev_w[0], 0);
    gemm_bf16<<<dim3(MID_DIM / TN, B_ROWS / TM), 128, GEMM_SMEM>>>(
        px2, pwt + OFF_WIN, b_in, ph0, nullptr, nullptr,
        HALF_DIM, MID_DIM, HALF_DIM / KC, 0);

    // hidden layers [4096,4096,4096]
    for (int i = 0; i < NH; i++) {
        const __nv_bfloat16* Ain = (i % 2 == 0) ? ph0 : ph1;
        __nv_bfloat16* Cc        = (i % 2 == 0) ? ph1 : ph0;
        cudaStreamWaitEvent(0, ev_w[1 + i], 0);
        gemm_bf16<<<dim3(MID_DIM / TN, B_ROWS / TM), 128, GEMM_SMEM>>>(
            Ain, pwt + OFF_WH + (size_t)i * MID_DIM * MID_DIM,
            b_h + (size_t)i * MID_DIM, Cc, nullptr, nullptr,
            MID_DIM, MID_DIM, MID_DIM / KC, 0);
    }

    // L6: y = interleave(x1 + h @ W_out + b_out, x2)   [M=4096, N=1024, K=4096]
    cudaStreamWaitEvent(0, ev_w[5], 0);
    gemm_bf16<<<dim3(HALF_DIM / TN, B_ROWS / TM), 128, GEMM_SMEM>>>(
        ph0, pwt + OFF_WOUT, b_out, nullptr, x, y,
        MID_DIM, HALF_DIM, MID_DIM / KC, 1);
}